// round 3
// baseline (speedup 1.0000x reference)
#include <cuda_runtime.h>

// 5-level db4 DWT, symmetric extension. Per-row cascade in smem with
// shift-by-2 padded buffers: signal at q[8] (16B aligned), left pad q[2..7],
// right pad after signal. 4 outputs/thread from 4 aligned LDS.128.

#define NROWS    4096
#define NT       256

#define L0 4096
#define L1 2051
#define L2 1029
#define L3 518
#define L4 262
#define L5 134

#define O_APPROX 0
#define O_D5 (NROWS * L5)
#define O_D4 (O_D5 + NROWS * L5)
#define O_D3 (O_D4 + NROWS * L4)
#define O_D2 (O_D3 + NROWS * L3)
#define O_D1 (O_D2 + NROWS * L2)

__global__ __launch_bounds__(NT)
void wavelet5_kernel(const float* __restrict__ x, float* __restrict__ out);

// Reversed filters: y[j] = sum_r RF[r] * ext[2j + r]
__device__ __forceinline__ void taps(const float w[14], float lo[4], float hi[4]) {
    const float RLO[8] = { 0.23037781330885523f,  0.7148465705525415f,
                           0.6308807679295904f,  -0.02798376941698385f,
                          -0.18703481171888114f,  0.030841381835986965f,
                           0.032883011666982945f,-0.010597401784997278f};
    const float RHI[8] = {-0.010597401784997278f,-0.032883011666982945f,
                           0.030841381835986965f, 0.18703481171888114f,
                          -0.02798376941698385f, -0.6308807679295904f,
                           0.7148465705525415f,  -0.23037781330885523f};
#pragma unroll
    for (int m = 0; m < 4; m++) {
        float l = RLO[0] * w[2 * m];
        float h = RHI[0] * w[2 * m];
#pragma unroll
        for (int r = 1; r < 8; r++) {
            l = fmaf(RLO[r], w[2 * m + r], l);
            h = fmaf(RHI[r], w[2 * m + r], h);
        }
        lo[m] = l;
        hi[m] = h;
    }
}

// One level. q = padded input (ext[i] = q[i+2], signal M_in long).
// M = number of outputs. cD -> gmem. cA -> next padded smem buffer (with
// mirror pads written inline), or gmem when LAST.
template<bool LAST>
__device__ __forceinline__ void dwt4(const float* __restrict__ q, int M,
                                     float* __restrict__ nxt,
                                     float* __restrict__ cD, int tid) {
    const float4* __restrict__ q4 = reinterpret_cast<const float4*>(q);
    const int NP4 = (M + 3) >> 2;
    for (int pi = tid; pi < NP4; pi += NT) {
        const float4 A = q4[2 * pi];
        const float4 B = q4[2 * pi + 1];
        const float4 C = q4[2 * pi + 2];
        const float4 D = q4[2 * pi + 3];
        // w[k] = ext[8pi + k] = q[8pi + 2 + k]
        const float w[14] = {A.z, A.w, B.x, B.y, B.z, B.w, C.x,
                             C.y, C.z, C.w, D.x, D.y, D.z, D.w};
        float lo[4], hi[4];
        taps(w, lo, hi);

        const int j0 = 4 * pi;
        if (j0 + 4 <= M) {
#pragma unroll
            for (int m = 0; m < 4; m++) cD[j0 + m] = hi[m];
            if (LAST) {
#pragma unroll
                for (int m = 0; m < 4; m++) nxt[j0 + m] = lo[m];
            } else {
                *reinterpret_cast<float4*>(nxt + 8 + j0) =
                    make_float4(lo[0], lo[1], lo[2], lo[3]);
            }
        } else {
#pragma unroll
            for (int m = 0; m < 4; m++) {
                const int j = j0 + m;
                if (j < M) {
                    cD[j] = hi[m];
                    if (LAST) nxt[j] = lo[m];
                    else      nxt[8 + j] = lo[m];
                }
            }
        }
        if (!LAST) {
            // Left mirror pad: ext[t] = cA[5-t] -> nxt[2+t], t=0..5
            if (pi == 0) { nxt[7] = lo[0]; nxt[6] = lo[1]; nxt[5] = lo[2]; nxt[4] = lo[3]; }
            else if (pi == 1) { nxt[3] = lo[0]; nxt[2] = lo[1]; }
            // Right mirror pad: ext[M+6+t] = cA[M-1-t] -> nxt[M+8+t], t=0..7
            if (j0 + 3 >= M - 8) {
#pragma unroll
                for (int m = 0; m < 4; m++) {
                    const int j = j0 + m;
                    if (j >= M - 8 && j < M) nxt[2 * M + 7 - j] = lo[m];
                }
            }
        }
    }
}

__global__ __launch_bounds__(NT)
void wavelet5_kernel(const float* __restrict__ x, float* __restrict__ out) {
    __shared__ __align__(16) float qA[L0 + 32];
    __shared__ __align__(16) float qB[L1 + 33];

    const int row = blockIdx.x;
    const int tid = threadIdx.x;
    const float* __restrict__ xr = x + (size_t)row * L0;

    // qA = shifted padded extension of the row: signal at qA[8..8+L0-1]
    {
        const float4* __restrict__ x4 = reinterpret_cast<const float4*>(xr);
        float4* __restrict__ p4 = reinterpret_cast<float4*>(qA + 8);
#pragma unroll 4
        for (int i = tid; i < L0 / 4; i += NT) p4[i] = x4[i];
        if (tid < 6) {
            qA[2 + tid] = xr[5 - tid];                 // left pad ext[0..5]
        } else if (tid < 14) {
            const int i = L0 + 2 + tid;                // q idx L0+8 .. L0+15
            qA[i] = xr[2 * L0 + 7 - i];                // right pad
        }
    }
    __syncthreads();

    float* __restrict__ d1 = out + O_D1 + (size_t)row * L1;
    float* __restrict__ d2 = out + O_D2 + (size_t)row * L2;
    float* __restrict__ d3 = out + O_D3 + (size_t)row * L3;
    float* __restrict__ d4 = out + O_D4 + (size_t)row * L4;
    float* __restrict__ d5 = out + O_D5 + (size_t)row * L5;
    float* __restrict__ ap = out + O_APPROX + (size_t)row * L5;

    dwt4<false>(qA, L1, qB, d1, tid);   // 4096 -> 2051
    __syncthreads();
    dwt4<false>(qB, L2, qA, d2, tid);   // 2051 -> 1029
    __syncthreads();
    dwt4<false>(qA, L3, qB, d3, tid);   // 1029 -> 518
    __syncthreads();
    dwt4<false>(qB, L4, qA, d4, tid);   // 518  -> 262
    __syncthreads();
    dwt4<true>(qA, L5, ap, d5, tid);    // 262  -> 134
}

extern "C" void kernel_launch(void* const* d_in, const int* in_sizes, int n_in,
                              void* d_out, int out_size) {
    const float* x = (const float*)d_in[0];
    float* out = (float*)d_out;
    (void)in_sizes; (void)n_in; (void)out_size;
    wavelet5_kernel<<<NROWS, NT>>>(x, out);
}

// round 4
// speedup vs baseline: 1.0089x; 1.0089x over previous
#include <cuda_runtime.h>

// 5-level db4 DWT, symmetric ext. Polyphase smem layout: each level's
// extended signal stored as E[i]=ext[2i], O[i]=ext[2i+1] with a per-level
// runtime shift s=(row*L_out)&3 so that loads (2x float4 per array) and
// cD global stores (STG.128) are both 16B-aligned and conflict-free.

#define NROWS 4096
#define NT    256

#define L0 4096
#define L1 2051
#define L2 1029
#define L3 518
#define L4 262
#define L5 134

#define O_APPROX 0
#define O_D5 (NROWS * L5)
#define O_D4 (O_D5 + NROWS * L5)
#define O_D3 (O_D4 + NROWS * L4)
#define O_D2 (O_D3 + NROWS * L3)
#define O_D1 (O_D2 + NROWS * L2)

// Reversed filter RF[r]=DEC[7-r]; y[j] = sum_k RFE[k]*E[j+k] + RFO[k]*O[j+k]
#define FLE0  0.23037781330885523f
#define FLE1  0.6308807679295904f
#define FLE2 -0.18703481171888114f
#define FLE3  0.032883011666982945f
#define FLO0  0.7148465705525415f
#define FLO1 -0.02798376941698385f
#define FLO2  0.030841381835986965f
#define FLO3 -0.010597401784997278f

#define FHE0 -0.010597401784997278f
#define FHE1  0.030841381835986965f
#define FHE2 -0.02798376941698385f
#define FHE3  0.7148465705525415f
#define FHO0 -0.032883011666982945f
#define FHO1  0.18703481171888114f
#define FHO2 -0.6308807679295904f
#define FHO3 -0.23037781330885523f

// One level: read polyphase arrays (shift s), produce M outputs.
// cD -> gmem (STG.128 interior). cA -> next polyphase arrays (shift sn) with
// mirror pads written inline, or to gmem (LAST).
template<bool LAST>
__device__ __forceinline__ void dwt_poly(
    const float* __restrict__ Ea, const float* __restrict__ Oa, int s,
    float* __restrict__ En, float* __restrict__ On, int sn,
    float* __restrict__ cD, float* __restrict__ cAg,
    int M, int tid)
{
    const float4* __restrict__ E4 = reinterpret_cast<const float4*>(Ea);
    const float4* __restrict__ O4 = reinterpret_cast<const float4*>(Oa);
    const int NPT = (M + s + 3) >> 2;
    const int Mn = (M + 7) >> 1;       // next-level output count
    const int iOmax = (M + 4) >> 1;    // last interior index of next O array

    for (int t = tid; t < NPT; t += NT) {
        const float4 ea = E4[t], eb = E4[t + 1];
        const float4 oa = O4[t], ob = O4[t + 1];
        const float e[8] = {ea.x, ea.y, ea.z, ea.w, eb.x, eb.y, eb.z, eb.w};
        const float o[8] = {oa.x, oa.y, oa.z, oa.w, ob.x, ob.y, ob.z, ob.w};
        float lo[4], hi[4];
#pragma unroll
        for (int m = 0; m < 4; m++) {
            float l = FLE0 * e[m];
            l = fmaf(FLE1, e[m + 1], l);
            l = fmaf(FLE2, e[m + 2], l);
            l = fmaf(FLE3, e[m + 3], l);
            l = fmaf(FLO0, o[m], l);
            l = fmaf(FLO1, o[m + 1], l);
            l = fmaf(FLO2, o[m + 2], l);
            l = fmaf(FLO3, o[m + 3], l);
            lo[m] = l;
            float h = FHE0 * e[m];
            h = fmaf(FHE1, e[m + 1], h);
            h = fmaf(FHE2, e[m + 2], h);
            h = fmaf(FHE3, e[m + 3], h);
            h = fmaf(FHO0, o[m], h);
            h = fmaf(FHO1, o[m + 1], h);
            h = fmaf(FHO2, o[m + 2], h);
            h = fmaf(FHO3, o[m + 3], h);
            hi[m] = h;
        }

        const int j0 = 4 * t - s;
        if (j0 >= 0 && j0 + 3 < M) {
            *reinterpret_cast<float4*>(cD + j0) =
                make_float4(hi[0], hi[1], hi[2], hi[3]);
            if (LAST)
                *reinterpret_cast<float4*>(cAg + j0) =
                    make_float4(lo[0], lo[1], lo[2], lo[3]);
        } else {
#pragma unroll
            for (int m = 0; m < 4; m++) {
                const int j = j0 + m;
                if (j >= 0 && j < M) {
                    cD[j] = hi[m];
                    if (LAST) cAg[j] = lo[m];
                }
            }
        }

        if (!LAST) {
            // Interior deinterleaved cA writes: a[j] even -> En[j/2+3], odd -> On[(j-1)/2+3]
#pragma unroll
            for (int m = 0; m < 4; m++) {
                const int j = j0 + m;
                if (j >= 0 && j < M) {
                    if (j & 1) On[sn + ((j - 1) >> 1) + 3] = lo[m];
                    else       En[sn + (j >> 1) + 3] = lo[m];
                }
            }
            // Mirror pads (boundary threads only)
            if (j0 <= 5 || j0 + 3 >= M - 8) {
#pragma unroll
                for (int m = 0; m < 4; m++) {
                    const int j = j0 + m;
                    if (j < 0 || j >= M) continue;
                    if (j <= 5) {
                        // left: E'[0..2]=a[5],a[3],a[1]; O'[0..2]=a[4],a[2],a[0]
                        if (j & 1) En[sn + ((5 - j) >> 1)] = lo[m];
                        else       On[sn + ((4 - j) >> 1)] = lo[m];
                    }
                    if (j >= M - 8) {
                        if (j & 1) {
                            const int i = (2 * M + 5 - j) >> 1;
                            if (i >= Mn && i <= Mn + 2) En[sn + i] = lo[m];
                        } else {
                            const int i = (2 * M + 4 - j) >> 1;
                            if (i > iOmax && i <= Mn + 2) On[sn + i] = lo[m];
                        }
                    }
                }
            }
        }
    }
}

__global__ __launch_bounds__(NT)
void wavelet5_kernel(const float* __restrict__ x, float* __restrict__ out) {
    __shared__ __align__(16) float EA_[2064], OA_[2064];  // levels 1,3,5
    __shared__ __align__(16) float EB_[1040], OB_[1040];  // levels 2,4

    const int row = blockIdx.x;
    const int tid = threadIdx.x;
    const float* __restrict__ xr = x + (size_t)row * L0;

    // Per-level alignment shifts: s = (row * L_out) & 3
    const int s1 = (row * 3) & 3;  // L1=2051 ≡ 3 (mod 4)
    const int s2 = row & 3;        // L2=1029 ≡ 1
    const int s3 = (row * 2) & 3;  // L3=518  ≡ 2
    const int s4 = s3;             // L4=262  ≡ 2
    const int s5 = s3;             // L5=134  ≡ 2

    // Fill level-1 polyphase arrays from gmem: E[i+3]=x[2i], O[i+3]=x[2i+1]
    {
        const float4* __restrict__ x4 = reinterpret_cast<const float4*>(xr);
#pragma unroll 4
        for (int u = tid; u < L0 / 4; u += NT) {
            const float4 v = x4[u];
            EA_[s1 + 3 + 2 * u] = v.x;
            OA_[s1 + 3 + 2 * u] = v.y;
            EA_[s1 + 4 + 2 * u] = v.z;
            OA_[s1 + 4 + 2 * u] = v.w;
        }
        if (tid < 3) {
            // left pads: E[t]=x[5-2t], O[t]=x[4-2t]
            EA_[s1 + tid] = xr[5 - 2 * tid];
            OA_[s1 + tid] = xr[4 - 2 * tid];
        } else if (tid < 6) {
            // right pads at i = 2051..2053 (Mn for 4096 is 2051)
            const int i = 2051 + (tid - 3);
            EA_[s1 + i] = xr[8197 - 2 * i];
            OA_[s1 + i] = xr[8196 - 2 * i];
        }
    }
    __syncthreads();

    float* __restrict__ d1 = out + O_D1 + (size_t)row * L1;
    float* __restrict__ d2 = out + O_D2 + (size_t)row * L2;
    float* __restrict__ d3 = out + O_D3 + (size_t)row * L3;
    float* __restrict__ d4 = out + O_D4 + (size_t)row * L4;
    float* __restrict__ d5 = out + O_D5 + (size_t)row * L5;
    float* __restrict__ ap = out + O_APPROX + (size_t)row * L5;

    dwt_poly<false>(EA_, OA_, s1, EB_, OB_, s2, d1, nullptr, L1, tid);
    __syncthreads();
    dwt_poly<false>(EB_, OB_, s2, EA_, OA_, s3, d2, nullptr, L2, tid);
    __syncthreads();
    dwt_poly<false>(EA_, OA_, s3, EB_, OB_, s4, d3, nullptr, L3, tid);
    __syncthreads();
    dwt_poly<false>(EB_, OB_, s4, EA_, OA_, s5, d4, nullptr, L4, tid);
    __syncthreads();
    dwt_poly<true>(EA_, OA_, s5, nullptr, nullptr, 0, d5, ap, L5, tid);
}

extern "C" void kernel_launch(void* const* d_in, const int* in_sizes, int n_in,
                              void* d_out, int out_size) {
    const float* x = (const float*)d_in[0];
    float* out = (float*)d_out;
    (void)in_sizes; (void)n_in; (void)out_size;
    wavelet5_kernel<<<NROWS, NT>>>(x, out);
}

// round 5
// speedup vs baseline: 1.4006x; 1.3883x over previous
#include <cuda_runtime.h>
#include <cuda_fp16.h>

// 5-level db4 DWT, symmetric extension. fp16 smem cascade (fp32 math, fp32
// gmem outputs). Per level: 4 outputs/thread, window = 14 halfs loaded as
// 2 conflict-free aligned LDS.128 (16B lane stride). Per-row shift sigma
// aligns cD to STG.128; smem offset c = ((2*sigma+4)&7)+6 keeps loads aligned.

#define NROWS 4096
#define NT    256

#define L0 4096
#define L1 2051
#define L2 1029
#define L3 518
#define L4 262
#define L5 134

#define O_APPROX 0
#define O_D5 (NROWS * L5)
#define O_D4 (O_D5 + NROWS * L5)
#define O_D3 (O_D4 + NROWS * L4)
#define O_D2 (O_D3 + NROWS * L3)
#define O_D1 (O_D2 + NROWS * L2)

// Reversed filters: y[j] = sum_r RF[r] * ext[2j + r]
#define RLO0  0.23037781330885523f
#define RLO1  0.7148465705525415f
#define RLO2  0.6308807679295904f
#define RLO3 -0.02798376941698385f
#define RLO4 -0.18703481171888114f
#define RLO5  0.030841381835986965f
#define RLO6  0.032883011666982945f
#define RLO7 -0.010597401784997278f

#define RHI0 -0.010597401784997278f
#define RHI1 -0.032883011666982945f
#define RHI2  0.030841381835986965f
#define RHI3  0.18703481171888114f
#define RHI4 -0.02798376941698385f
#define RHI5 -0.6308807679295904f
#define RHI6  0.7148465705525415f
#define RHI7 -0.23037781330885523f

__device__ __forceinline__ int coff(int s) { return ((2 * s + 4) & 7) + 6; }

// One level. q: fp16 buffer, ext[i] = q[c+i], input length N, M=(N+7)/2 outputs.
// cD -> fp32 gmem (STG.128 via sigma shift). Non-LAST: cA -> fp16 buffer qn
// (ext base cn) incl. mirror pads. LAST: cA -> fp32 gmem cAg (same sigma).
template<bool LAST>
__device__ __forceinline__ void dwt16(const __half* __restrict__ q, int c,
                                      int N, int sigma,
                                      __half* __restrict__ qn, int cn,
                                      float* __restrict__ cD,
                                      float* __restrict__ cAg, int tid)
{
    const int M  = (N + 7) >> 1;
    const int NB = (M + sigma + 3) >> 2;
    for (int T = tid; T < NB; T += NT) {
        const int j0 = 4 * T - sigma;
        const int h0 = c + 8 * T - 2 * sigma - 2;   // ≡ 0 (mod 8) by choice of c
        const uint4 u0 = *reinterpret_cast<const uint4*>(q + h0);
        const uint4 u1 = *reinterpret_cast<const uint4*>(q + h0 + 8);

        float w[14];
        {
            const __half2* ha = reinterpret_cast<const __half2*>(&u0);
            const __half2* hb = reinterpret_cast<const __half2*>(&u1);
            float2 t;
            t = __half22float2(ha[1]); w[0]  = t.x; w[1]  = t.y;
            t = __half22float2(ha[2]); w[2]  = t.x; w[3]  = t.y;
            t = __half22float2(ha[3]); w[4]  = t.x; w[5]  = t.y;
            t = __half22float2(hb[0]); w[6]  = t.x; w[7]  = t.y;
            t = __half22float2(hb[1]); w[8]  = t.x; w[9]  = t.y;
            t = __half22float2(hb[2]); w[10] = t.x; w[11] = t.y;
            t = __half22float2(hb[3]); w[12] = t.x; w[13] = t.y;
        }

        float lo[4], hi[4];
#pragma unroll
        for (int m = 0; m < 4; m++) {
            float l = RLO0 * w[2 * m];
            l = fmaf(RLO1, w[2 * m + 1], l);
            l = fmaf(RLO2, w[2 * m + 2], l);
            l = fmaf(RLO3, w[2 * m + 3], l);
            l = fmaf(RLO4, w[2 * m + 4], l);
            l = fmaf(RLO5, w[2 * m + 5], l);
            l = fmaf(RLO6, w[2 * m + 6], l);
            l = fmaf(RLO7, w[2 * m + 7], l);
            lo[m] = l;
            float h = RHI0 * w[2 * m];
            h = fmaf(RHI1, w[2 * m + 1], h);
            h = fmaf(RHI2, w[2 * m + 2], h);
            h = fmaf(RHI3, w[2 * m + 3], h);
            h = fmaf(RHI4, w[2 * m + 4], h);
            h = fmaf(RHI5, w[2 * m + 5], h);
            h = fmaf(RHI6, w[2 * m + 6], h);
            h = fmaf(RHI7, w[2 * m + 7], h);
            hi[m] = h;
        }

        const bool interior = (j0 >= 0) && (j0 + 4 <= M);
        if (interior) {
            *reinterpret_cast<float4*>(cD + j0) =
                make_float4(hi[0], hi[1], hi[2], hi[3]);
            if (LAST)
                *reinterpret_cast<float4*>(cAg + j0) =
                    make_float4(lo[0], lo[1], lo[2], lo[3]);
        } else {
#pragma unroll
            for (int m = 0; m < 4; m++) {
                const int j = j0 + m;
                if (j >= 0 && j < M) {
                    cD[j] = hi[m];
                    if (LAST) cAg[j] = lo[m];
                }
            }
        }

        if (!LAST) {
            if (interior && j0 > 5 && j0 + 3 < M - 8) {
#pragma unroll
                for (int m = 0; m < 4; m++)
                    qn[cn + 6 + j0 + m] = __float2half_rn(lo[m]);
            } else {
#pragma unroll
                for (int m = 0; m < 4; m++) {
                    const int j = j0 + m;
                    if (j < 0 || j >= M) continue;
                    const __half v = __float2half_rn(lo[m]);
                    qn[cn + 6 + j] = v;                      // interior
                    if (j <= 5)      qn[cn + 5 - j] = v;     // left mirror
                    if (j >= M - 8)  qn[cn + 2 * M + 5 - j] = v; // right mirror
                }
            }
        }
    }
}

__global__ __launch_bounds__(NT)
void wavelet5_kernel(const float* __restrict__ x, float* __restrict__ out) {
    __shared__ __align__(16) __half IN16[4160];  // lvl1 input / lvl3 output / lvl4 input
    __shared__ __align__(16) __half A16[2112];   // lvl1 out / lvl2 in / lvl4 out / lvl5 in
    __shared__ __align__(16) __half B16[1088];   // lvl2 out / lvl3 in

    const int row = blockIdx.x;
    const int tid = threadIdx.x;

    // Per-level gmem alignment shifts (floats mod 4 of each cD row base)
    const int s1 = (3 * row) & 3;   // L1=2051 ≡ 3 (mod 4)
    const int s2 = row & 3;         // L2=1029 ≡ 1
    const int s3 = (2 * row) & 3;   // L3,L4,L5 ≡ 2
    const int c1 = coff(s1), c2 = coff(s2), c3 = coff(s3);

    const float* __restrict__ xr = x + (size_t)row * L0;

    // Build fp16 extended input: ext[i] = IN16[c1+i]
    {
        const float4* __restrict__ x4 = reinterpret_cast<const float4*>(xr);
        __half2* __restrict__ dst = reinterpret_cast<__half2*>(IN16 + c1 + 6);
#pragma unroll 4
        for (int u = tid; u < L0 / 4; u += NT) {
            const float4 v = x4[u];
            dst[2 * u]     = __floats2half2_rn(v.x, v.y);
            dst[2 * u + 1] = __floats2half2_rn(v.z, v.w);
        }
        if (tid < 6) {
            IN16[c1 + tid] = __float2half_rn(xr[5 - tid]);            // left ext
        } else if (tid < 14) {
            const int t = tid - 6;
            IN16[c1 + L0 + 6 + t] = __float2half_rn(xr[L0 - 1 - t]);  // right ext
        }
    }
    __syncthreads();

    float* __restrict__ d1 = out + O_D1 + (size_t)row * L1;
    float* __restrict__ d2 = out + O_D2 + (size_t)row * L2;
    float* __restrict__ d3 = out + O_D3 + (size_t)row * L3;
    float* __restrict__ d4 = out + O_D4 + (size_t)row * L4;
    float* __restrict__ d5 = out + O_D5 + (size_t)row * L5;
    float* __restrict__ ap = out + O_APPROX + (size_t)row * L5;

    dwt16<false>(IN16, c1, L0, s1, A16, c2, d1, nullptr, tid);  // 4096 -> 2051
    __syncthreads();
    dwt16<false>(A16, c2, L1, s2, B16, c3, d2, nullptr, tid);   // 2051 -> 1029
    __syncthreads();
    dwt16<false>(B16, c3, L2, s3, IN16, c3, d3, nullptr, tid);  // 1029 -> 518
    __syncthreads();
    dwt16<false>(IN16, c3, L3, s3, A16, c3, d4, nullptr, tid);  // 518  -> 262
    __syncthreads();
    dwt16<true>(A16, c3, L4, s3, nullptr, 0, d5, ap, tid);      // 262  -> 134
}

extern "C" void kernel_launch(void* const* d_in, const int* in_sizes, int n_in,
                              void* d_out, int out_size) {
    const float* x = (const float*)d_in[0];
    float* out = (float*)d_out;
    (void)in_sizes; (void)n_in; (void)out_size;
    wavelet5_kernel<<<NROWS, NT>>>(x, out);
}